// round 16
// baseline (speedup 1.0000x reference)
#include <cuda_runtime.h>
#include <cstdint>

#define HWD   21952              // 28^3
#define BSTR  2809856            // 128*HWD
#define NG    87808              // 4*HWD = 256 windows * 343
#define ATT_SCALE 0.17677669529663687f

// dynamic smem for attention: q,k,v [32][343] + probs [64][343] + rinv[64] + osp[343]
#define ATTN_SMEM_FLOATS (3*10976 + 64*343 + 64 + 343)
#define ATTN_SMEM_BYTES  (ATTN_SMEM_FLOATS * 4)

// ---------------- scratch (device globals: the sanctioned workaround) ----------------
__device__ float g_qkv[384u * 87808u];     // rows 0..127 q, 128..255 k, 256..383 relu(v)
__device__ float g_attn[128u * 87808u];    // attention output, layout [C][B*spatial]
__device__ float g_yb[128u * 87808u];      // conv3d output, layout [C][B*spatial]
__device__ float g_wt[3456 * 128];         // conv weight transposed [k = t*128+c][m], tf32-truncated
__device__ float g_wqkv[128 * 384];        // qkv weight transposed: [k][m] (m: 0..255 qk, 256..383 v)
__device__ float g_wp[128 * 128];          // proj weight transposed: [k][m]
__device__ float g_bn[512];                // [0:128) sc1 [128:256) sh1 [256:384) sc2 [384:512) sh2

__device__ __forceinline__ float silu_f(float v) {
    return v / (1.0f + __expf(-v));
}

__device__ __forceinline__ uint32_t f2tf32(float f) {
    uint32_t r;
    asm("cvt.rna.tf32.f32 %0, %1;" : "=r"(r) : "f"(f));
    return r;
}

__device__ __forceinline__ void mma_tf32(float& d0, float& d1, float& d2, float& d3,
                                         uint32_t a0, uint32_t a1, uint32_t a2, uint32_t a3,
                                         uint32_t b0, uint32_t b1) {
    asm volatile("mma.sync.aligned.m16n8k8.row.col.f32.tf32.tf32.f32 "
                 "{%0,%1,%2,%3}, {%4,%5,%6,%7}, {%8,%9}, {%0,%1,%2,%3};"
                 : "+f"(d0), "+f"(d1), "+f"(d2), "+f"(d3)
                 : "r"(a0), "r"(a1), "r"(a2), "r"(a3), "r"(b0), "r"(b1));
}

// ===================== BN stats on input x (B,C,H,W,D) =====================
__global__ __launch_bounds__(256) void bn_stats_in_kernel(const float* __restrict__ x,
                                                          const float* __restrict__ gamma,
                                                          const float* __restrict__ beta)
{
    int c = blockIdx.x;
    float s = 0.f, s2 = 0.f;
    for (int b = 0; b < 4; ++b) {
        const float* p = x + (size_t)b * BSTR + (size_t)c * HWD;
        for (int i = threadIdx.x; i < HWD; i += 256) {
            float v = p[i];
            s += v; s2 += v * v;
        }
    }
    __shared__ float rs[256], rq[256];
    rs[threadIdx.x] = s; rq[threadIdx.x] = s2;
    __syncthreads();
    for (int o = 128; o > 0; o >>= 1) {
        if (threadIdx.x < o) {
            rs[threadIdx.x] += rs[threadIdx.x + o];
            rq[threadIdx.x] += rq[threadIdx.x + o];
        }
        __syncthreads();
    }
    if (threadIdx.x == 0) {
        const float inv = 1.f / (4.f * (float)HWD);
        float m   = rs[0] * inv;
        float var = rq[0] * inv - m * m;
        float r   = rsqrtf(var + 1e-6f);
        float sc  = gamma[c] * r;
        g_bn[c]       = sc;
        g_bn[128 + c] = beta[c] - m * sc;
    }
}

// ===================== BN stats on conv output g_yb [C][NG] =====================
__global__ __launch_bounds__(256) void bn_stats_y_kernel(const float* __restrict__ gamma,
                                                         const float* __restrict__ beta)
{
    int c = blockIdx.x;
    const float* p = g_yb + (size_t)c * NG;
    float s = 0.f, s2 = 0.f;
    for (int i = threadIdx.x; i < NG; i += 256) {
        float v = p[i];
        s += v; s2 += v * v;
    }
    __shared__ float rs[256], rq[256];
    rs[threadIdx.x] = s; rq[threadIdx.x] = s2;
    __syncthreads();
    for (int o = 128; o > 0; o >>= 1) {
        if (threadIdx.x < o) {
            rs[threadIdx.x] += rs[threadIdx.x + o];
            rq[threadIdx.x] += rq[threadIdx.x + o];
        }
        __syncthreads();
    }
    if (threadIdx.x == 0) {
        const float inv = 1.f / (float)NG;
        float m   = rs[0] * inv;
        float var = rq[0] * inv - m * m;
        float r   = rsqrtf(var + 1e-6f);
        float sc  = gamma[c] * r;
        g_bn[256 + c] = sc;
        g_bn[384 + c] = beta[c] - m * sc;
    }
}

// ===================== weight transposes =====================
__global__ __launch_bounds__(256) void wt_kernel(const float* __restrict__ w_cl)
{
    int idx = blockIdx.x * 256 + threadIdx.x;   // 3456*128 = 442368
    if (idx < 3456 * 128) {
        int k = idx >> 7;
        int m = idx & 127;
        int t = k >> 7;
        int c = k & 127;
        g_wt[idx] = __uint_as_float(f2tf32(w_cl[(size_t)m * 3456 + c * 27 + t]));
    }
}

__global__ __launch_bounds__(256) void wqkv_kernel(const float* __restrict__ w_qk,
                                                   const float* __restrict__ w_v)
{
    int idx = blockIdx.x * 256 + threadIdx.x;   // 128*384 = 49152
    if (idx < 128 * 384) {
        int k = idx / 384;
        int m = idx - k * 384;
        g_wqkv[idx] = (m < 256) ? w_qk[(size_t)m * 128 + k]
                                : w_v[(size_t)(m - 256) * 128 + k];
    }
}

__global__ __launch_bounds__(256) void wp_kernel(const float* __restrict__ w_proj)
{
    int idx = blockIdx.x * 256 + threadIdx.x;   // 128*128 = 16384
    if (idx < 128 * 128) {
        int k = idx >> 7;
        int m = idx & 127;
        g_wp[idx] = w_proj[(size_t)m * 128 + k];
    }
}

// ===================== QKV GEMM: [384x128] @ bn(windowed x)[128 x 87808], 128x128 tile =====================
__global__ __launch_bounds__(256, 2) void qkv_gemm_kernel(const float* __restrict__ x)
{
    __shared__ __align__(16) float As[16][128];
    __shared__ __align__(16) float Bs[16][128];
    __shared__ int colbase[128];
    int tid = threadIdx.x;
    int n0 = blockIdx.x * 128;
    int m0 = blockIdx.y * 128;
    if (tid < 128) {
        int n = n0 + tid;
        int w = n / 343;
        int l = n - w * 343;
        int b0 = w >> 6, rem = w & 63;
        int wa = rem >> 4, wb = (rem >> 2) & 3, wc = rem & 3;
        int i = l / 49; int r2 = l - i * 49;
        int j = r2 / 7; int kx = r2 - j * 7;
        colbase[tid] = b0 * BSTR + (i*4 + wa) * 784 + (j*4 + wb) * 28 + (kx*4 + wc);
    }
    __syncthreads();

    int ty = tid >> 4, tx = tid & 15;
    int kkb = tid >> 4, jb = (tid & 15) << 3;
    int akk0 = tid >> 5, acol0 = (tid & 31) << 2;
    int akk1 = akk0 + 8;

    float acc[8][8];
#pragma unroll
    for (int r = 0; r < 8; ++r)
#pragma unroll
        for (int c = 0; c < 8; ++c) acc[r][c] = 0.f;

    for (int k0 = 0; k0 < 128; k0 += 16) {
        *(float4*)&As[akk0][acol0] = *(const float4*)(g_wqkv + (size_t)(k0 + akk0) * 384 + m0 + acol0);
        *(float4*)&As[akk1][acol0] = *(const float4*)(g_wqkv + (size_t)(k0 + akk1) * 384 + m0 + acol0);
        int kg = k0 + kkb;
        float scv = g_bn[kg], shv = g_bn[128 + kg];
        const float* xk = x + (size_t)kg * HWD;
#pragma unroll
        for (int j = 0; j < 8; ++j)
            Bs[kkb][jb + j] = fmaf(xk[colbase[jb + j]], scv, shv);
        __syncthreads();
#pragma unroll
        for (int kk = 0; kk < 16; ++kk) {
            float4 a0 = *(const float4*)&As[kk][ty * 8];
            float4 a1 = *(const float4*)&As[kk][ty * 8 + 4];
            float4 b0 = *(const float4*)&Bs[kk][tx * 8];
            float4 b1 = *(const float4*)&Bs[kk][tx * 8 + 4];
            float av[8] = {a0.x, a0.y, a0.z, a0.w, a1.x, a1.y, a1.z, a1.w};
            float bv[8] = {b0.x, b0.y, b0.z, b0.w, b1.x, b1.y, b1.z, b1.w};
#pragma unroll
            for (int r = 0; r < 8; ++r)
#pragma unroll
                for (int c = 0; c < 8; ++c)
                    acc[r][c] = fmaf(av[r], bv[c], acc[r][c]);
        }
        __syncthreads();
    }

    bool dorelu = (m0 >= 256);
#pragma unroll
    for (int r = 0; r < 8; ++r) {
        int m = m0 + ty * 8 + r;
        float* dst = g_qkv + (size_t)m * NG + n0 + tx * 8;
        float4 o0, o1;
        o0.x = acc[r][0]; o0.y = acc[r][1]; o0.z = acc[r][2]; o0.w = acc[r][3];
        o1.x = acc[r][4]; o1.y = acc[r][5]; o1.z = acc[r][6]; o1.w = acc[r][7];
        if (dorelu) {
            o0.x = fmaxf(o0.x, 0.f); o0.y = fmaxf(o0.y, 0.f);
            o0.z = fmaxf(o0.z, 0.f); o0.w = fmaxf(o0.w, 0.f);
            o1.x = fmaxf(o1.x, 0.f); o1.y = fmaxf(o1.y, 0.f);
            o1.z = fmaxf(o1.z, 0.f); o1.w = fmaxf(o1.w, 0.f);
        }
        *(float4*)dst = o0;
        *(float4*)(dst + 4) = o1;
    }
}

// ===================== Attention: one block per (window, head) — R11 proven version =====================
__global__ __launch_bounds__(256) void attn_kernel()
{
    extern __shared__ float sm[];
    float* qs   = sm;                  // [32][343]
    float* ks   = sm + 10976;
    float* vs   = sm + 2 * 10976;
    float* ps   = sm + 3 * 10976;      // [64][343]
    float* rinv = ps + 64 * 343;       // [64]
    int*   osp  = (int*)(rinv + 64);   // [343]

    int tid = threadIdx.x;
    int w = blockIdx.x >> 2, h = blockIdx.x & 3;
    int b0 = w >> 6, rem = w & 63;
    int wa = rem >> 4, wb = (rem >> 2) & 3, wc = rem & 3;

    int gq = (h * 32) * NG + w * 343;
    for (int idx = tid; idx < 10976; idx += 256) {
        int d = idx / 343, l = idx - d * 343;
        int g = gq + d * NG + l;
        qs[idx] = g_qkv[g];
        ks[idx] = g_qkv[g + 128 * NG];
        vs[idx] = g_qkv[g + 256 * NG];
    }
    for (int l = tid; l < 343; l += 256) {
        int i = l / 49, r2 = l - i * 49;
        int j = r2 / 7, kx = r2 - j * 7;
        osp[l] = b0 * HWD + (i*4 + wa) * 784 + (j*4 + wb) * 28 + (kx*4 + wc);
    }
    __syncthreads();

    int ty   = tid >> 4, tx  = tid & 15;
    int lane = tid & 31, wp  = tid >> 5;
    int ty32 = tid >> 3, tx8 = tid & 7;

    for (int g = 0; g < 6; ++g) {
        int l0 = g * 64;
        int lidx[4];
#pragma unroll
        for (int r = 0; r < 4; ++r) lidx[r] = min(l0 + ty*4 + r, 342);

        for (int pass = 0; pass < 3; ++pass) {
            int mc[8]; bool mok[8];
#pragma unroll
            for (int c = 0; c < 8; ++c) {
                int mr = pass*128 + tx + c*16;
                mok[c] = (mr < 343);
                mc[c] = mok[c] ? mr : 342;
            }
            float accs[4][8];
#pragma unroll
            for (int r = 0; r < 4; ++r)
#pragma unroll
                for (int c = 0; c < 8; ++c) accs[r][c] = 0.f;
#pragma unroll 4
            for (int d = 0; d < 32; ++d) {
                float qv[4], kv[8];
#pragma unroll
                for (int r = 0; r < 4; ++r) qv[r] = qs[d*343 + lidx[r]];
#pragma unroll
                for (int c = 0; c < 8; ++c) kv[c] = ks[d*343 + mc[c]];
#pragma unroll
                for (int r = 0; r < 4; ++r)
#pragma unroll
                    for (int c = 0; c < 8; ++c)
                        accs[r][c] = fmaf(qv[r], kv[c], accs[r][c]);
            }
#pragma unroll
            for (int r = 0; r < 4; ++r)
#pragma unroll
                for (int c = 0; c < 8; ++c)
                    if (mok[c]) ps[(ty*4 + r)*343 + mc[c]] = accs[r][c] * ATT_SCALE;
        }
        __syncthreads();

        for (int r8 = 0; r8 < 8; ++r8) {
            int rr = wp * 8 + r8;
            float mx = -1e30f;
            for (int m = lane; m < 343; m += 32) mx = fmaxf(mx, ps[rr*343 + m]);
#pragma unroll
            for (int o = 16; o > 0; o >>= 1) mx = fmaxf(mx, __shfl_xor_sync(0xffffffffu, mx, o));
            float s = 0.f;
            for (int m = lane; m < 343; m += 32) {
                float p = __expf(ps[rr*343 + m] - mx);
                ps[rr*343 + m] = p;
                s += p;
            }
#pragma unroll
            for (int o = 16; o > 0; o >>= 1) s += __shfl_xor_sync(0xffffffffu, s, o);
            if (lane == 0) rinv[rr] = 1.f / s;
        }
        __syncthreads();

        float acco[2][4];
#pragma unroll
        for (int r = 0; r < 2; ++r)
#pragma unroll
            for (int j = 0; j < 4; ++j) acco[r][j] = 0.f;
        int rr0 = ty32 * 2;
        int d0  = tx8 * 4;
#pragma unroll 2
        for (int m = 0; m < 343; ++m) {
            float p0 = ps[rr0*343 + m];
            float p1 = ps[(rr0+1)*343 + m];
            float vv[4];
#pragma unroll
            for (int j = 0; j < 4; ++j) vv[j] = vs[(d0 + j)*343 + m];
#pragma unroll
            for (int j = 0; j < 4; ++j) {
                acco[0][j] = fmaf(p0, vv[j], acco[0][j]);
                acco[1][j] = fmaf(p1, vv[j], acco[1][j]);
            }
        }
#pragma unroll
        for (int r = 0; r < 2; ++r) {
            int l = l0 + rr0 + r;
            if (l < 343) {
                float ri = rinv[rr0 + r];
                int sp = osp[l];
#pragma unroll
                for (int j = 0; j < 4; ++j)
                    g_attn[(size_t)(h*32 + d0 + j) * NG + sp] = acco[r][j] * ri;
            }
        }
        __syncthreads();
    }
}

// ===================== conv3d 3x3x3 (128->128), TF32 mma.sync, 128x128 tile =====================
// K ordered tap-major: k = t*128 + c. 8 warps in 2x4; warp tile 64x32 via 4x4 m16n8k8 tiles.
__global__ __launch_bounds__(256, 2) void conv3d_kernel()
{
    __shared__ __align__(16) float afrag[2048];  // [(mt*2+ks)*32 + lane]*4 + e
    __shared__ __align__(16) float bfrag[2048];  // [(nt*2+ks)*32 + lane]*2 + e
    __shared__ int shh[128], sww[128], sdd[128];

    int tid = threadIdx.x;
    int n0 = blockIdx.x * 128;

    if (tid < 128) {
        int n = n0 + tid;
        int b = n / HWD; int sp = n - b * HWD;
        int hh = sp / 784; int r2 = sp - hh * 784;
        int ww = r2 / 28;  int dd = r2 - ww * 28;
        shh[tid] = hh; sww[tid] = ww; sdd[tid] = dd;
    }
    __syncthreads();

    // fill roles (same global access pattern as the proven FFMA version)
    int akk0 = tid >> 5,  acol0 = (tid & 31) << 2;   // A: k-rows akk0/akk1, m-cols acol0..+3
    int akk1 = akk0 + 8;
    int kkb  = tid >> 4,  jb = (tid & 15) << 3;      // B: k-row kkb, n-cols jb..+7

    // chunk-invariant scatter addresses into fragment layouts
    int aaddr0[4], aaddr1[4], baddr[8];
#pragma unroll
    for (int i = 0; i < 4; ++i) {
        int m = acol0 + i;
        int mt = m >> 4, mr = m & 15;
        {
            int ks = akk0 >> 3, kc = akk0 & 7;
            int ln = ((mr & 7) << 2) | (kc & 3);
            int e  = (mr >> 3) | ((kc >> 2) << 1);
            aaddr0[i] = ((mt * 2 + ks) * 32 + ln) * 4 + e;
        }
        {
            int ks = akk1 >> 3, kc = akk1 & 7;
            int ln = ((mr & 7) << 2) | (kc & 3);
            int e  = (mr >> 3) | ((kc >> 2) << 1);
            aaddr1[i] = ((mt * 2 + ks) * 32 + ln) * 4 + e;
        }
    }
#pragma unroll
    for (int j = 0; j < 8; ++j) {
        int n = jb + j;
        int ks = kkb >> 3, kc = kkb & 7, nt = n >> 3, nr = n & 7;
        int ln = (nr << 2) | (kc & 3);
        int e  = kc >> 2;
        baddr[j] = ((nt * 2 + ks) * 32 + ln) * 2 + e;
    }

    // compute roles
    int lane = tid & 31, wid = tid >> 5;
    int wy = wid >> 2, wx = wid & 3;

    float4 aR0, aR1;
    float  bR[8];

    // ---- prefetch chunk 0 (tap 0: dh=dw=dz=-1, c0=0) ----
    aR0 = *(const float4*)(g_wt + (size_t)akk0 * 128 + acol0);
    aR1 = *(const float4*)(g_wt + (size_t)akk1 * 128 + acol0);
    {
        const int dh = -1, dw = -1, dz = -1;
        const int delta = dh * 784 + dw * 28 + dz;
        const float* src = g_attn + (size_t)kkb * NG + n0 + delta;
#pragma unroll
        for (int j = 0; j < 8; ++j) {
            int jj = jb + j;
            bool ok = (unsigned)(shh[jj] + dh) < 28u &&
                      (unsigned)(sww[jj] + dw) < 28u &&
                      (unsigned)(sdd[jj] + dz) < 28u;
            bR[j] = ok ? src[jj] : 0.f;
        }
    }

    float d[4][4][4];
#pragma unroll
    for (int i = 0; i < 4; ++i)
#pragma unroll
        for (int j = 0; j < 4; ++j)
#pragma unroll
            for (int e = 0; e < 4; ++e) d[i][j][e] = 0.f;

    for (int k0 = 0; k0 < 3456; k0 += 16) {
        // ---- commit prefetched regs to fragment smem ----
        float av0[4] = {aR0.x, aR0.y, aR0.z, aR0.w};
        float av1[4] = {aR1.x, aR1.y, aR1.z, aR1.w};
#pragma unroll
        for (int i = 0; i < 4; ++i) {
            afrag[aaddr0[i]] = av0[i];
            afrag[aaddr1[i]] = av1[i];
        }
#pragma unroll
        for (int j = 0; j < 8; ++j)
            bfrag[baddr[j]] = __uint_as_float(f2tf32(bR[j]));
        __syncthreads();

        // ---- prefetch next chunk ----
        int k1 = k0 + 16;
        if (k1 < 3456) {
            aR0 = *(const float4*)(g_wt + (size_t)(k1 + akk0) * 128 + acol0);
            aR1 = *(const float4*)(g_wt + (size_t)(k1 + akk1) * 128 + acol0);
            int t  = k1 >> 7;
            int c0 = k1 & 127;
            int dh = t / 9 - 1;
            int r3 = t % 9;
            int dw = r3 / 3 - 1;
            int dz = r3 % 3 - 1;
            int delta = dh * 784 + dw * 28 + dz;
            const float* src = g_attn + (size_t)(c0 + kkb) * NG + n0 + delta;
#pragma unroll
            for (int j = 0; j < 8; ++j) {
                int jj = jb + j;
                bool ok = (unsigned)(shh[jj] + dh) < 28u &&
                          (unsigned)(sww[jj] + dw) < 28u &&
                          (unsigned)(sdd[jj] + dz) < 28u;
                bR[j] = ok ? src[jj] : 0.f;
            }
        }

        // ---- compute: 2 ksteps x (4 mt x 4 nt) mma ----
#pragma unroll
        for (int ks = 0; ks < 2; ++ks) {
            uint32_t A[4][4];
#pragma unroll
            for (int i = 0; i < 4; ++i) {
                int mt = wy * 4 + i;
                float4 fa = *(const float4*)&afrag[((mt * 2 + ks) * 32 + lane) * 4];
                A[i][0] = __float_as_uint(fa.x);
                A[i][1] = __float_as_uint(fa.y);
                A[i][2] = __float_as_uint(fa.z);
                A[i][3] = __float_as_uint(fa.w);
            }
            uint32_t B[4][2];
#pragma unroll
            for (int j = 0; j < 4; ++j) {
                int nt = wx * 4 + j;
                float2 fb = *(const float2*)&bfrag[((nt * 2 + ks) * 32 + lane) * 2];
                B[j][0] = __float_as_uint(fb.x);
                B[j][1] = __float_as_uint(fb.y);
            }
#pragma unroll
            for (int i = 0; i < 4; ++i)
#pragma unroll
                for (int j = 0; j < 4; ++j)
                    mma_tf32(d[i][j][0], d[i][j][1], d[i][j][2], d[i][j][3],
                             A[i][0], A[i][1], A[i][2], A[i][3],
                             B[j][0], B[j][1]);
        }
        __syncthreads();
    }

    // ---- store: thread holds rows (lane>>2, +8), cols (lane&3)*2, +1 of each 16x8 tile ----
    int r0 = lane >> 2;
    int cc = (lane & 3) * 2;
#pragma unroll
    for (int i = 0; i < 4; ++i) {
        int mrow = (wy * 4 + i) * 16 + r0;
#pragma unroll
        for (int j = 0; j < 4; ++j) {
            int n = n0 + (wx * 4 + j) * 8 + cc;
            float2 v0; v0.x = d[i][j][0]; v0.y = d[i][j][1];
            float2 v1; v1.x = d[i][j][2]; v1.y = d[i][j][3];
            *(float2*)(g_yb + (size_t)mrow * NG + n) = v0;
            *(float2*)(g_yb + (size_t)(mrow + 8) * NG + n) = v1;
        }
    }
}

// ===================== final: out = x + w_proj @ (attn + silu(bn(yb))), 128x128 tile =====================
__global__ __launch_bounds__(256, 2) void final_kernel(const float* __restrict__ x,
                                                       float* __restrict__ out)
{
    __shared__ __align__(16) float As[16][128];
    __shared__ __align__(16) float Bs[16][128];
    int tid = threadIdx.x;
    int n0 = blockIdx.x * 128;

    int ty = tid >> 4, tx = tid & 15;
    int kkb = tid >> 4, jb = (tid & 15) << 3;
    int akk0 = tid >> 5, acol0 = (tid & 31) << 2;
    int akk1 = akk0 + 8;

    float acc[8][8];
#pragma unroll
    for (int r = 0; r < 8; ++r)
#pragma unroll
        for (int c = 0; c < 8; ++c) acc[r][c] = 0.f;

    for (int k0 = 0; k0 < 128; k0 += 16) {
        *(float4*)&As[akk0][acol0] = *(const float4*)(g_wp + (size_t)(k0 + akk0) * 128 + acol0);
        *(float4*)&As[akk1][acol0] = *(const float4*)(g_wp + (size_t)(k0 + akk1) * 128 + acol0);
        int i = k0 + kkb;
        float sc = g_bn[256 + i], sh = g_bn[384 + i];
        const float* yrow = g_yb   + (size_t)i * NG + n0 + jb;
        const float* arow = g_attn + (size_t)i * NG + n0 + jb;
        float4 ya0 = *(const float4*)yrow;
        float4 ya1 = *(const float4*)(yrow + 4);
        float4 aa0 = *(const float4*)arow;
        float4 aa1 = *(const float4*)(arow + 4);
        float4 t0, t1;
        t0.x = aa0.x + silu_f(fmaf(ya0.x, sc, sh));
        t0.y = aa0.y + silu_f(fmaf(ya0.y, sc, sh));
        t0.z = aa0.z + silu_f(fmaf(ya0.z, sc, sh));
        t0.w = aa0.w + silu_f(fmaf(ya0.w, sc, sh));
        t1.x = aa1.x + silu_f(fmaf(ya1.x, sc, sh));
        t1.y = aa1.y + silu_f(fmaf(ya1.y, sc, sh));
        t1.z = aa1.z + silu_f(fmaf(ya1.z, sc, sh));
        t1.w = aa1.w + silu_f(fmaf(ya1.w, sc, sh));
        *(float4*)&Bs[kkb][jb]     = t0;
        *(float4*)&Bs[kkb][jb + 4] = t1;
        __syncthreads();
#pragma unroll
        for (int kk = 0; kk < 16; ++kk) {
            float4 a0 = *(const float4*)&As[kk][ty * 8];
            float4 a1 = *(const float4*)&As[kk][ty * 8 + 4];
            float4 b0 = *(const float4*)&Bs[kk][tx * 8];
            float4 b1 = *(const float4*)&Bs[kk][tx * 8 + 4];
            float av[8] = {a0.x, a0.y, a0.z, a0.w, a1.x, a1.y, a1.z, a1.w};
            float bv[8] = {b0.x, b0.y, b0.z, b0.w, b1.x, b1.y, b1.z, b1.w};
#pragma unroll
            for (int r = 0; r < 8; ++r)
#pragma unroll
                for (int c = 0; c < 8; ++c)
                    acc[r][c] = fmaf(av[r], bv[c], acc[r][c]);
        }
        __syncthreads();
    }

    int n = n0 + tx * 8;
    int b = n / HWD;
    int sp = n - b * HWD;
#pragma unroll
    for (int r = 0; r < 8; ++r) {
        int m = ty * 8 + r;
        size_t o = (size_t)b * BSTR + (size_t)m * HWD + sp;
        float4 x0 = *(const float4*)(x + o);
        float4 x1 = *(const float4*)(x + o + 4);
        float4 o0, o1;
        o0.x = x0.x + acc[r][0]; o0.y = x0.y + acc[r][1];
        o0.z = x0.z + acc[r][2]; o0.w = x0.w + acc[r][3];
        o1.x = x1.x + acc[r][4]; o1.y = x1.y + acc[r][5];
        o1.z = x1.z + acc[r][6]; o1.w = x1.w + acc[r][7];
        *(float4*)(out + o) = o0;
        *(float4*)(out + o + 4) = o1;
    }
}

// ===================== launch =====================
extern "C" void kernel_launch(void* const* d_in, const int* in_sizes, int n_in,
                              void* d_out, int out_size)
{
    const float* x      = (const float*)d_in[0];
    const float* g_in   = (const float*)d_in[1];
    const float* b_in   = (const float*)d_in[2];
    const float* w_qk   = (const float*)d_in[3];
    const float* w_v    = (const float*)d_in[4];
    const float* w_cl   = (const float*)d_in[5];
    const float* g_cl   = (const float*)d_in[6];
    const float* b_cl   = (const float*)d_in[7];
    const float* w_proj = (const float*)d_in[8];
    float* out = (float*)d_out;

    cudaFuncSetAttribute(attn_kernel, cudaFuncAttributeMaxDynamicSharedMemorySize,
                         ATTN_SMEM_BYTES);

    bn_stats_in_kernel<<<128, 256>>>(x, g_in, b_in);
    wt_kernel<<<1728, 256>>>(w_cl);
    wqkv_kernel<<<192, 256>>>(w_qk, w_v);
    wp_kernel<<<64, 256>>>(w_proj);
    qkv_gemm_kernel<<<dim3(686, 3), 256>>>(x);
    attn_kernel<<<1024, 256, ATTN_SMEM_BYTES>>>();
    conv3d_kernel<<<686, 256>>>();
    bn_stats_y_kernel<<<128, 256>>>(g_cl, b_cl);
    final_kernel<<<686, 256>>>(x, out);
}